// round 6
// baseline (speedup 1.0000x reference)
#include <cuda_runtime.h>

// BSplineTransformation: x (16,3,1024,1024) f32, control_points (1,2,35,35) f32
// out = concat(transformed (16,3,1024,1024), deformation_field (2,1024,1024))

#define HH 1024
#define WW 1024
#define NPIX (HH*WW)
#define NB 16
#define NC 3
#define CP 35
#define CP2 (CP*CP)
#define BATCHES_PER_BLOCK 4
#define ROW_SPLIT (NPIX/2)   // second pixel is 512 rows below the first

__global__ __launch_bounds__(256) void bspline_kernel(
    const float* __restrict__ x,
    const float* __restrict__ cp,
    float* __restrict__ out)
{
    __shared__ float scp[2*CP2];
    for (int t = threadIdx.x; t < 2*CP2; t += 256) scp[t] = cp[t];
    __syncthreads();

    // thread handles pixels p and p+ROW_SPLIT (rows i and i+512, same column)
    const int p = blockIdx.x * 256 + threadIdx.x;

    int   qa00, qa01, qa10, qa11, qb00, qb01, qb10, qb11;
    float axa, aya, axb, ayb;

    #pragma unroll
    for (int half = 0; half < 2; half++) {
        const int pp = p + half * ROW_SPLIT;
        const int i = pp >> 10;
        const int j = pp & 1023;
        const float gy = fmaf((float)i, 2.0f / 1023.0f, -1.0f);
        const float gx = fmaf((float)j, 2.0f / 1023.0f, -1.0f);

        // ---- deformation: grid_sample(control_points, border, align_corners) ----
        const float cx = (gx + 1.0f) * 17.0f;
        const float cy = (gy + 1.0f) * 17.0f;
        float icx = fminf(fmaxf((cx + 1.0f) * 17.0f, 0.0f), 34.0f);
        float icy = fminf(fmaxf((cy + 1.0f) * 17.0f, 0.0f), 34.0f);
        const float fcx = floorf(icx);
        const float fcy = floorf(icy);
        const int cx0 = (int)fcx;
        const int cy0 = (int)fcy;
        const int cx1 = min(cx0 + 1, CP - 1);
        const int cy1 = min(cy0 + 1, CP - 1);
        const float wx = icx - fcx;
        const float wy = icy - fcy;

        const int o00 = cy0 * CP + cx0;
        const int o01 = cy0 * CP + cx1;
        const int o10 = cy1 * CP + cx0;
        const int o11 = cy1 * CP + cx1;

        const float t0 = fmaf(wx, scp[o01] - scp[o00], scp[o00]);
        const float b0 = fmaf(wx, scp[o11] - scp[o10], scp[o10]);
        const float d0 = fmaf(wy, b0 - t0, t0);
        const float t1 = fmaf(wx, scp[CP2+o01] - scp[CP2+o00], scp[CP2+o00]);
        const float b1 = fmaf(wx, scp[CP2+o11] - scp[CP2+o10], scp[CP2+o10]);
        const float d1 = fmaf(wy, b1 - t1, t1);

        if (blockIdx.y == 0) {
            float* def = out + (long long)NB * NC * NPIX;
            def[pp]        = d0;
            def[NPIX + pp] = d1;
        }

        float sx = fminf(fmaxf((gx + d1 + 1.0f) * 511.5f, 0.0f), 1023.0f);
        float sy = fminf(fmaxf((gy + d0 + 1.0f) * 511.5f, 0.0f), 1023.0f);
        const float fsx = floorf(sx);
        const float fsy = floorf(sy);
        const int ix0 = (int)fsx;
        const int iy0 = (int)fsy;
        const int ix1 = min(ix0 + 1, WW - 1);
        const int iy1 = min(iy0 + 1, HH - 1);
        const float ax = sx - fsx;
        const float ay = sy - fsy;
        const int q00 = (iy0 << 10) + ix0;
        const int q01 = (iy0 << 10) + ix1;
        const int q10 = (iy1 << 10) + ix0;
        const int q11 = (iy1 << 10) + ix1;

        if (half == 0) { qa00=q00; qa01=q01; qa10=q10; qa11=q11; axa=ax; aya=ay; }
        else           { qb00=q00; qb01=q01; qb10=q10; qb11=q11; axb=ax; ayb=ay; }
    }

    // ---- 12 images, 8 independent gathers in flight per image ----
    const int img_start = blockIdx.y * BATCHES_PER_BLOCK * NC;

    #pragma unroll
    for (int m = 0; m < BATCHES_PER_BLOCK * NC; m++) {
        const float* im = x + ((long long)(img_start + m) << 20);
        const float a00 = __ldg(im + qa00);
        const float a01 = __ldg(im + qa01);
        const float a10 = __ldg(im + qa10);
        const float a11 = __ldg(im + qa11);
        const float c00 = __ldg(im + qb00);
        const float c01 = __ldg(im + qb01);
        const float c10 = __ldg(im + qb10);
        const float c11 = __ldg(im + qb11);

        const float topa = fmaf(axa, a01 - a00, a00);
        const float bota = fmaf(axa, a11 - a10, a10);
        const float ra   = fmaf(aya, bota - topa, topa);
        const float topb = fmaf(axb, c01 - c00, c00);
        const float botb = fmaf(axb, c11 - c10, c10);
        const float rb   = fmaf(ayb, botb - topb, topb);

        float* ob = out + ((long long)(img_start + m) << 20);
        ob[p]             = ra;
        ob[p + ROW_SPLIT] = rb;
    }
}

extern "C" void kernel_launch(void* const* d_in, const int* in_sizes, int n_in,
                              void* d_out, int out_size)
{
    const float* x  = (const float*)d_in[0];
    const float* cp = (const float*)d_in[1];
    float* out = (float*)d_out;

    dim3 grid(ROW_SPLIT / 256, NB / BATCHES_PER_BLOCK);
    bspline_kernel<<<grid, 256>>>(x, cp, out);
}

// round 7
// speedup vs baseline: 1.0970x; 1.0970x over previous
#include <cuda_runtime.h>

// BSplineTransformation: x (16,3,1024,1024) f32, control_points (1,2,35,35) f32
// out = concat(transformed (16,3,1024,1024), deformation_field (2,1024,1024))

#define HH 1024
#define WW 1024
#define NPIX (HH*WW)
#define NB 16
#define NC 3
#define NIMG (NB*NC)
#define CP 35
#define CP2 (CP*CP)

__global__ __launch_bounds__(256) void bspline_kernel(
    const float* __restrict__ x,
    const float* __restrict__ cp,
    float* __restrict__ out)
{
    __shared__ float scp[2*CP2];
    for (int t = threadIdx.x; t < 2*CP2; t += 256) scp[t] = cp[t];
    __syncthreads();

    const int p = blockIdx.x * 256 + threadIdx.x;   // pixel index; thread does ALL 48 images
    const int i = p >> 10;
    const int j = p & 1023;

    const float gy = fmaf((float)i, 2.0f / 1023.0f, -1.0f);
    const float gx = fmaf((float)j, 2.0f / 1023.0f, -1.0f);

    // ---- deformation field: grid_sample(control_points, border, align_corners) ----
    const float cx = (gx + 1.0f) * 17.0f;
    const float cy = (gy + 1.0f) * 17.0f;
    float icx = fminf(fmaxf((cx + 1.0f) * 17.0f, 0.0f), 34.0f);
    float icy = fminf(fmaxf((cy + 1.0f) * 17.0f, 0.0f), 34.0f);
    const float fcx = floorf(icx);
    const float fcy = floorf(icy);
    const int cx0 = (int)fcx;
    const int cy0 = (int)fcy;
    const int cx1 = min(cx0 + 1, CP - 1);
    const int cy1 = min(cy0 + 1, CP - 1);
    const float wx = icx - fcx;
    const float wy = icy - fcy;

    const int o00 = cy0 * CP + cx0;
    const int o01 = cy0 * CP + cx1;
    const int o10 = cy1 * CP + cx0;
    const int o11 = cy1 * CP + cx1;

    const float t0 = fmaf(wx, scp[o01] - scp[o00], scp[o00]);
    const float b0 = fmaf(wx, scp[o11] - scp[o10], scp[o10]);
    const float d0 = fmaf(wy, b0 - t0, t0);
    const float t1 = fmaf(wx, scp[CP2+o01] - scp[CP2+o00], scp[CP2+o00]);
    const float b1 = fmaf(wx, scp[CP2+o11] - scp[CP2+o10], scp[CP2+o10]);
    const float d1 = fmaf(wy, b1 - t1, t1);

    // deformation field output (once per pixel)
    {
        float* def = out + (long long)NIMG * NPIX;
        def[p]        = d0;
        def[NPIX + p] = d1;
    }

    // ---- main sample coords (shared by all 48 images) ----
    float sx = fminf(fmaxf((gx + d1 + 1.0f) * 511.5f, 0.0f), 1023.0f);
    float sy = fminf(fmaxf((gy + d0 + 1.0f) * 511.5f, 0.0f), 1023.0f);
    const float fsx = floorf(sx);
    const float fsy = floorf(sy);
    const int ix0 = (int)fsx;
    const int iy0 = (int)fsy;
    const int ix1 = min(ix0 + 1, WW - 1);
    const int iy1 = min(iy0 + 1, HH - 1);
    const float ax = sx - fsx;
    const float ay = sy - fsy;

    const int q00 = (iy0 << 10) + ix0;
    const int q01 = (iy0 << 10) + ix1;
    const int q10 = (iy1 << 10) + ix0;
    const int q11 = (iy1 << 10) + ix1;

    // ---- 48 images, pointer-bump loop, same 4-load pattern as the R2 optimum ----
    const float* im = x;
    float*       ob = out + p;

    #pragma unroll
    for (int m = 0; m < NIMG; m++) {
        const float v00 = __ldg(im + q00);
        const float v01 = __ldg(im + q01);
        const float v10 = __ldg(im + q10);
        const float v11 = __ldg(im + q11);
        const float top = fmaf(ax, v01 - v00, v00);
        const float bot = fmaf(ax, v11 - v10, v10);
        *ob = fmaf(ay, bot - top, top);
        im += NPIX;
        ob += NPIX;
    }
}

extern "C" void kernel_launch(void* const* d_in, const int* in_sizes, int n_in,
                              void* d_out, int out_size)
{
    const float* x  = (const float*)d_in[0];
    const float* cp = (const float*)d_in[1];
    float* out = (float*)d_out;

    bspline_kernel<<<NPIX / 256, 256>>>(x, cp, out);
}